// round 7
// baseline (speedup 1.0000x reference)
#include <cuda_runtime.h>
#include <cstdint>

#define BATCH   8192
#define FEAT    128
#define DEG     32
#define KSEL    16
#define EMB     128

// ---------------- scratch (static device arrays; no allocation) ----------------
__device__ float g_xbuf[BATCH * FEAT];          // self feats   [B,128]
__device__ float g_agg [3 * BATCH * FEAT];      // agg feats    [3,B,128]
__device__ float g_cs0 [BATCH];                 // center class-0 score

// ---------------- f32x2 packed-FMA helpers (Blackwell FFMA2 via PTX) ----------------
__device__ __forceinline__ unsigned long long pk2(float x, float y) {
    unsigned int xu = __float_as_uint(x), yu = __float_as_uint(y);
    unsigned long long r;
    asm("mov.b64 %0, {%1, %2};" : "=l"(r) : "r"(xu), "r"(yu));
    return r;
}
__device__ __forceinline__ void upk2(unsigned long long v, float& x, float& y) {
    unsigned int lo, hi;
    asm("mov.b64 {%0, %1}, %2;" : "=r"(lo), "=r"(hi) : "l"(v));
    x = __uint_as_float(lo);
    y = __uint_as_float(hi);
}
__device__ __forceinline__ void ffma2(unsigned long long& d,
                                      unsigned long long a,
                                      unsigned long long b) {
    asm("fma.rn.f32x2 %0, %1, %2, %0;" : "+l"(d) : "l"(a), "l"(b));
}

// ---------------- Kernel A: self gather + center scores ----------------
__global__ void self_score_kernel(const float* __restrict__ feat,
                                  const float* __restrict__ Wclf,
                                  const float* __restrict__ bclf,
                                  const int*   __restrict__ nodes,
                                  float* __restrict__ out_cs) {
    int b = blockIdx.x;
    int t = threadIdx.x;                 // 128 threads
    long base = (long)__ldg(nodes + b) * FEAT;
    float v = __ldg(feat + base + t);
    g_xbuf[b * FEAT + t] = v;
    float p0 = v * __ldg(Wclf + 2 * t);
    float p1 = v * __ldg(Wclf + 2 * t + 1);
    #pragma unroll
    for (int o = 16; o; o >>= 1) {
        p0 += __shfl_xor_sync(0xffffffffu, p0, o);
        p1 += __shfl_xor_sync(0xffffffffu, p1, o);
    }
    __shared__ float s0[4], s1[4];
    int w = t >> 5;
    if ((t & 31) == 0) { s0[w] = p0; s1[w] = p1; }
    __syncthreads();
    if (t == 0) {
        float c0 = s0[0] + s0[1] + s0[2] + s0[3] + __ldg(bclf);
        float c1 = s1[0] + s1[1] + s1[2] + s1[3] + __ldg(bclf + 1);
        out_cs[b * 2]     = c0;
        out_cs[b * 2 + 1] = c1;
        g_cs0[b] = c0;
    }
}

// ---------------- Kernel B: neighbor gather + score + top-K select + mean ----------------
// One block per (b, rel). 128 threads. Each neighbor row is read from DRAM
// exactly once: score computed from registers while storing the row to smem.
__global__ __launch_bounds__(128) void agg_kernel(const float* __restrict__ feat,
                                                  const float* __restrict__ Wclf,
                                                  const float* __restrict__ bclf,
                                                  const int*   __restrict__ n1,
                                                  const int*   __restrict__ n2,
                                                  const int*   __restrict__ n3) {
    const int b   = blockIdx.x;
    const int rel = blockIdx.y;
    const int* nb = (rel == 0) ? n1 : (rel == 1) ? n2 : n3;

    __shared__ float    sf[DEG][132];   // pitch 132 avoids bank conflicts
    __shared__ float    sscore[DEG];
    __shared__ unsigned smask;

    int t = threadIdx.x;
    int w = t >> 5, l = t & 31;

    // W_clf column 0 (strided by 2) pieces for this lane's float4 slot
    float w00 = __ldg(Wclf + 8 * l);
    float w01 = __ldg(Wclf + 8 * l + 2);
    float w02 = __ldg(Wclf + 8 * l + 4);
    float w03 = __ldg(Wclf + 8 * l + 6);
    float bias0 = __ldg(bclf);
    float cs0 = g_cs0[b];

    // warp w handles neighbor rows n = w, w+4, ..., w+28 (8 rows, good MLP)
    #pragma unroll
    for (int r = 0; r < 8; r++) {
        int n = w + 4 * r;
        long idx = (long)__ldg(nb + b * DEG + n);
        float4 f = __ldg((const float4*)(feat + idx * FEAT) + l);
        *(float4*)&sf[n][4 * l] = f;
        float p = f.x * w00 + f.y * w01 + f.z * w02 + f.w * w03;
        #pragma unroll
        for (int o = 16; o; o >>= 1) p += __shfl_xor_sync(0xffffffffu, p, o);
        if (l == 0) sscore[n] = p + bias0;
    }
    __syncthreads();

    // rank-based selection of the K smallest |score - cs0| (index tiebreak
    // matches jax.lax.top_k's stable lower-index-first semantics)
    if (t < DEG) {
        float di = fabsf(sscore[t] - cs0);
        int rank = 0;
        #pragma unroll
        for (int j = 0; j < DEG; j++) {
            float dj = fabsf(sscore[j] - cs0);
            rank += (dj < di) || (dj == di && j < t);
        }
        unsigned m = __ballot_sync(0xffffffffu, rank < KSEL);
        if (t == 0) smask = m;
    }
    __syncthreads();

    unsigned m = smask;
    float sum = 0.f;
    #pragma unroll
    for (int n = 0; n < DEG; n++)
        if (m & (1u << n)) sum += sf[n][t];
    g_agg[((long)rel * BATCH + b) * FEAT + t] = sum * (1.0f / KSEL);
}

// ---------------- Kernel C: fused 3x intra GEMM + comb GEMM + relu + transpose ----------------
// 128 blocks, BM=64 rows each, 256 threads. A-tiles fully smem-resident;
// E_r overwrites agg_r in place; zero intermediate global traffic.
// Inner product uses packed f32x2 FMA (FFMA2): 4 rows x 4 column-pairs per thread.

#define APITCH 132   // smem row pitch (floats)

__device__ __forceinline__ void mma_chunk(const float* __restrict__ A,
                                          const float* __restrict__ sW,
                                          int c0, unsigned long long acc[4][4]) {
    // preload this thread's 4 A-rows for the 16-deep K chunk (vector LDS)
    float av[4][16];
    #pragma unroll
    for (int i = 0; i < 4; i++) {
        #pragma unroll
        for (int q = 0; q < 4; q++)
            *(float4*)&av[i][4 * q] = *(const float4*)&A[i * APITCH + 4 * q];
    }
    #pragma unroll
    for (int k2 = 0; k2 < 16; k2++) {
        ulonglong2 b01 = *(const ulonglong2*)&sW[k2 * 128 + c0];      // cols c0..c0+3
        ulonglong2 b23 = *(const ulonglong2*)&sW[k2 * 128 + c0 + 4];  // cols c0+4..c0+7
        unsigned long long bp0 = b01.x, bp1 = b01.y, bp2 = b23.x, bp3 = b23.y;
        #pragma unroll
        for (int i = 0; i < 4; i++) {
            unsigned long long ap = pk2(av[i][k2], av[i][k2]);
            ffma2(acc[i][0], ap, bp0);
            ffma2(acc[i][1], ap, bp1);
            ffma2(acc[i][2], ap, bp2);
            ffma2(acc[i][3], ap, bp3);
        }
    }
}

__device__ __forceinline__ void load_wchunk(const float* __restrict__ W, int kk,
                                            float* __restrict__ sW, int tid) {
    #pragma unroll
    for (int i = 0; i < 2; i++) {
        int e = tid + i * 256;                       // float4 index 0..511
        float4 v = __ldg((const float4*)(W + kk * 128) + e);
        *(float4*)&sW[e * 4] = v;
    }
}

__global__ __launch_bounds__(256, 1) void fused_gemm_kernel(const float* __restrict__ Wi1,
                                                            const float* __restrict__ Wi2,
                                                            const float* __restrict__ Wi3,
                                                            const float* __restrict__ Wc,
                                                            float* __restrict__ out) {
    extern __shared__ float smem[];
    float* sSelf = smem;                               // 64*APITCH
    float* sAgg0 = smem + 64 * APITCH;
    float* sAgg1 = smem + 2 * 64 * APITCH;
    float* sAgg2 = smem + 3 * 64 * APITCH;
    float* sW    = smem + 4 * 64 * APITCH;             // 16*128
    float* sAggs[3] = {sAgg0, sAgg1, sAgg2};

    const int tid = threadIdx.x;
    const int bm  = blockIdx.x * 64;

    // load self tile (64x128) — 8 float4 per thread, coalesced
    #pragma unroll
    for (int i = 0; i < 8; i++) {
        int e = tid + i * 256;        // float4 index
        int row = e >> 5;             // 32 float4 per row
        int c4  = e & 31;
        float4 v = __ldg((const float4*)(g_xbuf + (long)(bm + row) * FEAT) + c4);
        *(float4*)&sSelf[row * APITCH + c4 * 4] = v;
    }
    // load agg tiles
    #pragma unroll
    for (int rel = 0; rel < 3; rel++) {
        #pragma unroll
        for (int i = 0; i < 8; i++) {
            int e = tid + i * 256;
            int row = e >> 5;
            int c4  = e & 31;
            float4 v = __ldg((const float4*)(g_agg + ((long)rel * BATCH + bm + row) * FEAT) + c4);
            *(float4*)&sAggs[rel][row * APITCH + c4 * 4] = v;
        }
    }
    __syncthreads();

    // thread micro-tile: 4 rows x 8 cols (4 f32x2 pairs). lanes span cols ->
    // A-reads are 2-address broadcasts within a warp.
    const int colg = tid & 15, rowg = tid >> 4;
    const int r0 = rowg * 4, c0 = colg * 8;

    // ---- three intra GEMMs: E_r = relu([self || agg_r] @ W_r), overwrite agg_r ----
    #pragma unroll 1
    for (int rel = 0; rel < 3; rel++) {
        const float* W = (rel == 0) ? Wi1 : (rel == 1) ? Wi2 : Wi3;
        unsigned long long acc[4][4];
        #pragma unroll
        for (int i = 0; i < 4; i++)
            #pragma unroll
            for (int j = 0; j < 4; j++) acc[i][j] = 0ull;
        #pragma unroll 1
        for (int kk = 0; kk < 256; kk += 16) {
            load_wchunk(W, kk, sW, tid);
            __syncthreads();
            const float* A = (kk < 128) ? (sSelf + r0 * APITCH + kk)
                                        : (sAggs[rel] + r0 * APITCH + (kk - 128));
            mma_chunk(A, sW, c0, acc);
            __syncthreads();
        }
        // relu + overwrite agg_r with E_r (all reads of agg_r finished at last sync)
        #pragma unroll
        for (int i = 0; i < 4; i++)
            #pragma unroll
            for (int j = 0; j < 4; j++) {
                float x, y;
                upk2(acc[i][j], x, y);
                float2 v = make_float2(fmaxf(x, 0.f), fmaxf(y, 0.f));
                *(float2*)&sAggs[rel][(r0 + i) * APITCH + c0 + 2 * j] = v;
            }
        __syncthreads();
    }

    // ---- comb GEMM: relu([self||E1||E2||E3] @ Wc), write transposed [128, B] ----
    unsigned long long acc[4][4];
    #pragma unroll
    for (int i = 0; i < 4; i++)
        #pragma unroll
        for (int j = 0; j < 4; j++) acc[i][j] = 0ull;
    #pragma unroll 1
    for (int kk = 0; kk < 512; kk += 16) {
        load_wchunk(Wc, kk, sW, tid);
        __syncthreads();
        const float* A;
        if (kk < 128) A = sSelf + r0 * APITCH + kk;
        else          A = sAggs[(kk - 128) >> 7] + r0 * APITCH + ((kk - 128) & 127);
        mma_chunk(A, sW, c0, acc);
        __syncthreads();
    }
    // unpack, relu, transpose-store: 4 consecutive rows per column -> float4
    float f[4][8];
    #pragma unroll
    for (int i = 0; i < 4; i++)
        #pragma unroll
        for (int j = 0; j < 4; j++)
            upk2(acc[i][j], f[i][2 * j], f[i][2 * j + 1]);
    #pragma unroll
    for (int jj = 0; jj < 8; jj++) {
        float4 v = make_float4(fmaxf(f[0][jj], 0.f), fmaxf(f[1][jj], 0.f),
                               fmaxf(f[2][jj], 0.f), fmaxf(f[3][jj], 0.f));
        *(float4*)(out + (long)(c0 + jj) * BATCH + bm + r0) = v;
    }
}

// ---------------- launch ----------------
extern "C" void kernel_launch(void* const* d_in, const int* in_sizes, int n_in,
                              void* d_out, int out_size) {
    const float* feat  = (const float*)d_in[0];
    const float* Wclf  = (const float*)d_in[1];
    const float* bclf  = (const float*)d_in[2];
    const float* Wi1   = (const float*)d_in[3];
    const float* Wi2   = (const float*)d_in[4];
    const float* Wi3   = (const float*)d_in[5];
    const float* Wc    = (const float*)d_in[6];
    const int*   nodes = (const int*)d_in[7];
    const int*   n1    = (const int*)d_in[8];
    const int*   n2    = (const int*)d_in[9];
    const int*   n3    = (const int*)d_in[10];

    float* out    = (float*)d_out;
    float* out_cs = out + (long)EMB * BATCH;   // center_scores after combined

    self_score_kernel<<<BATCH, 128>>>(feat, Wclf, bclf, nodes, out_cs);

    dim3 gridB(BATCH, 3);
    agg_kernel<<<gridB, 128>>>(feat, Wclf, bclf, n1, n2, n3);

    int smemC = (4 * 64 * APITCH + 16 * 128) * sizeof(float);  // ~140 KB
    cudaFuncSetAttribute(fused_gemm_kernel,
                         cudaFuncAttributeMaxDynamicSharedMemorySize, smemC);
    fused_gemm_kernel<<<BATCH / 64, 256, smemC>>>(Wi1, Wi2, Wi3, Wc, out);
}